// round 1
// baseline (speedup 1.0000x reference)
#include <cuda_runtime.h>
#include <cstdint>
#include <cstddef>

// Problem constants
#define Bn 256
#define Sn 128
#define En 1024

// attn scratch (device global — no allocations allowed)
__device__ float g_attn[Bn * Sn];

// ---------------------------------------------------------------------------
// tf32 helpers (warp-level mma.sync, m16n8k8)
// ---------------------------------------------------------------------------
__device__ __forceinline__ uint32_t f2tf32(float f) {
    uint32_t r;
    asm("cvt.rna.tf32.f32 %0, %1;" : "=r"(r) : "f"(f));
    return r;
}

__device__ __forceinline__ void mma_tf32(float* c,
                                         uint32_t a0, uint32_t a1, uint32_t a2, uint32_t a3,
                                         uint32_t b0, uint32_t b1) {
    asm volatile(
        "mma.sync.aligned.m16n8k8.row.col.f32.tf32.tf32.f32 "
        "{%0,%1,%2,%3},{%4,%5,%6,%7},{%8,%9},{%0,%1,%2,%3};"
        : "+f"(c[0]), "+f"(c[1]), "+f"(c[2]), "+f"(c[3])
        : "r"(a0), "r"(a1), "r"(a2), "r"(a3), "r"(b0), "r"(b1));
}

// ---------------------------------------------------------------------------
// Kernel A: fused scores + softmax per batch.
//   One block per batch b. Block tile: M = 96 rows (the whole bag, len<=96),
//   N = 128 f-columns per chunk (8 chunks cover E=1024), K streamed in 32-wide
//   smem tiles. After each f-chunk's K sweep: scores += tanh(z) * u[f].
//   Warps with m-subtile >= ceil(len/16) skip the mma (mask-aware saving).
// ---------------------------------------------------------------------------
constexpr int MT = 96;
constexpr int NT = 128;
constexpr int KT = 32;
constexpr int KP = KT + 4;          // pad 4: bank = (4*row + k) % 32, conflict-free
constexpr int NTHR = 384;           // 12 warps: 6 (M) x 2 (N)
constexpr int WMN = 6;
constexpr int WNN = 2;
constexpr int WARP_N = NT / WNN;    // 64
constexpr int NMMA = WARP_N / 8;    // 8
constexpr int NCHUNK = En / NT;     // 8

__global__ __launch_bounds__(NTHR, 1)
void scores_kernel(const float* __restrict__ x,
                   const float* __restrict__ W,
                   const float* __restrict__ u,
                   const int* __restrict__ doc) {
    __shared__ uint32_t Asm_[MT][KP];
    __shared__ uint32_t Bsm_[NT][KP];
    __shared__ float    u_s[En];
    __shared__ float    s_part[MT][WNN];

    const int b   = blockIdx.x;
    const int tid = threadIdx.x;
    const int start = doc[2 * b];
    const int end   = doc[2 * b + 1];
    const int len   = end - start;          // 1..96
    const int nmt   = (len + 15) >> 4;      // active 16-row subtiles (1..6)

    for (int i = tid; i < En; i += NTHR) u_s[i] = u[i];
    for (int i = tid; i < MT * WNN; i += NTHR) ((float*)s_part)[i] = 0.0f;

    const int wid  = tid >> 5;
    const int lane = tid & 31;
    const int g    = lane >> 2;   // groupID (0..7)
    const int tg   = lane & 3;    // threadID_in_group (0..3)
    const int wm   = wid % WMN;   // M warp index (0..5)
    const int wn   = wid / WMN;   // N warp index (0..1)
    const bool active = (wm < nmt);
    const int row0 = wm * 16 + g;
    const int row1 = row0 + 8;

    float sacc0 = 0.0f, sacc1 = 0.0f;

    for (int fc = 0; fc < NCHUNK; fc++) {
        const int f0 = fc * NT;
        float c[NMMA][4];
        #pragma unroll
        for (int j = 0; j < NMMA; j++) {
            c[j][0] = 0.0f; c[j][1] = 0.0f; c[j][2] = 0.0f; c[j][3] = 0.0f;
        }

        for (int k0 = 0; k0 < En; k0 += KT) {
            __syncthreads();   // protect previous iteration's smem reads

            // Fill A: 96 x 32 (rows >= len zero-padded). 3072/384 = 8 per thread.
            #pragma unroll
            for (int it = 0; it < (MT * KT) / NTHR; it++) {
                int idx = it * NTHR + tid;
                int m  = idx / KT;
                int kk = idx % KT;
                float v = (m < len)
                    ? x[(size_t)(b * Sn + start + m) * En + (k0 + kk)]
                    : 0.0f;
                Asm_[m][kk] = f2tf32(v);
            }
            // Fill B: 128 x 32. 4096/384 -> 11 iters with guard.
            #pragma unroll
            for (int it = 0; it < (NT * KT + NTHR - 1) / NTHR; it++) {
                int idx = it * NTHR + tid;
                if (idx < NT * KT) {
                    int n  = idx / KT;
                    int kk = idx % KT;
                    Bsm_[n][kk] = f2tf32(W[(size_t)(f0 + n) * En + (k0 + kk)]);
                }
            }
            __syncthreads();

            if (active) {
                #pragma unroll
                for (int ks = 0; ks < KT; ks += 8) {
                    uint32_t a0 = Asm_[row0][ks + tg];
                    uint32_t a1 = Asm_[row1][ks + tg];
                    uint32_t a2 = Asm_[row0][ks + tg + 4];
                    uint32_t a3 = Asm_[row1][ks + tg + 4];
                    #pragma unroll
                    for (int j = 0; j < NMMA; j++) {
                        int nb = wn * WARP_N + j * 8 + g;
                        uint32_t b0 = Bsm_[nb][ks + tg];
                        uint32_t b1 = Bsm_[nb][ks + tg + 4];
                        mma_tf32(c[j], a0, a1, a2, a3, b0, b1);
                    }
                }
            }
        }

        if (active) {
            #pragma unroll
            for (int j = 0; j < NMMA; j++) {
                int f = f0 + wn * WARP_N + j * 8 + 2 * tg;
                sacc0 += tanhf(c[j][0]) * u_s[f] + tanhf(c[j][1]) * u_s[f + 1];
                sacc1 += tanhf(c[j][2]) * u_s[f] + tanhf(c[j][3]) * u_s[f + 1];
            }
        }
    }

    // Deterministic reduce across the 4 threads sharing a row (tg = 0..3).
    sacc0 += __shfl_xor_sync(0xffffffffu, sacc0, 1);
    sacc0 += __shfl_xor_sync(0xffffffffu, sacc0, 2);
    sacc1 += __shfl_xor_sync(0xffffffffu, sacc1, 1);
    sacc1 += __shfl_xor_sync(0xffffffffu, sacc1, 2);
    if (active && tg == 0) {
        s_part[row0][wn] = sacc0;
        s_part[row1][wn] = sacc1;
    }
    __syncthreads();

    // Softmax over the bag — warp 0, 3 rows per lane. Deterministic.
    if (wid == 0) {
        float v[3];
        #pragma unroll
        for (int i = 0; i < 3; i++) {
            int r = lane + 32 * i;
            v[i] = (r < len) ? (s_part[r][0] + s_part[r][1]) : -3.0e38f;
        }
        float mx = fmaxf(v[0], fmaxf(v[1], v[2]));
        #pragma unroll
        for (int o = 16; o > 0; o >>= 1)
            mx = fmaxf(mx, __shfl_xor_sync(0xffffffffu, mx, o));
        float e[3];
        float ssum = 0.0f;
        #pragma unroll
        for (int i = 0; i < 3; i++) {
            int r = lane + 32 * i;
            e[i] = (r < len) ? __expf(v[i] - mx) : 0.0f;
            ssum += e[i];
        }
        #pragma unroll
        for (int o = 16; o > 0; o >>= 1)
            ssum += __shfl_xor_sync(0xffffffffu, ssum, o);
        float inv = 1.0f / ssum;
        #pragma unroll
        for (int i = 0; i < 3; i++) {
            int r = lane + 32 * i;
            if (r < len) g_attn[b * Sn + start + r] = e[i] * inv;
        }
    }
}

// ---------------------------------------------------------------------------
// Kernel B: out_concat[b, :] = sum_{s in bag} attn[b,s] * x[b,s,:]
//   One block per batch; 256 threads x float4 = 1024 columns.
// ---------------------------------------------------------------------------
__global__ __launch_bounds__(256)
void out_kernel(const float4* __restrict__ x4,
                const int* __restrict__ doc,
                float* __restrict__ out) {
    const int b = blockIdx.x;
    const int t = threadIdx.x;
    const int start = doc[2 * b];
    const int end   = doc[2 * b + 1];
    float4 acc = make_float4(0.0f, 0.0f, 0.0f, 0.0f);
    for (int s = start; s < end; s++) {
        float a = g_attn[b * Sn + s];
        float4 xv = x4[(size_t)(b * Sn + s) * (En / 4) + t];
        acc.x += a * xv.x;
        acc.y += a * xv.y;
        acc.z += a * xv.z;
        acc.w += a * xv.w;
    }
    reinterpret_cast<float4*>(out)[(size_t)b * (En / 4) + t] = acc;
}

// ---------------------------------------------------------------------------
// Kernel C: keep_attention = attn[B-1] padded with zeros to length S.
// ---------------------------------------------------------------------------
__global__ void keep_kernel(const int* __restrict__ doc, float* __restrict__ out) {
    const int s = threadIdx.x;
    const int b = Bn - 1;
    const int start = doc[2 * b];
    const int end   = doc[2 * b + 1];
    out[(size_t)Bn * En + s] = (s >= start && s < end) ? g_attn[b * Sn + s] : 0.0f;
}

// ---------------------------------------------------------------------------
extern "C" void kernel_launch(void* const* d_in, const int* in_sizes, int n_in,
                              void* d_out, int out_size) {
    const float* x   = (const float*)d_in[0];
    const float* W   = (const float*)d_in[1];
    const float* u   = (const float*)d_in[2];
    const int*   doc = (const int*)d_in[3];
    float* out = (float*)d_out;

    scores_kernel<<<Bn, NTHR>>>(x, W, u, doc);
    out_kernel<<<Bn, 256>>>((const float4*)x, doc, out);
    keep_kernel<<<1, Sn>>>(doc, out);
}

// round 2
// speedup vs baseline: 2.0821x; 2.0821x over previous
#include <cuda_runtime.h>
#include <cuda_fp16.h>
#include <cstdint>
#include <cstddef>

#define Bn 256
#define Sn 128
#define En 1024

constexpr int MT   = 96;            // M rows per block (bag always fits: start<32, len<=96)
constexpr int NT   = 256;           // N (f) columns per chunk
constexpr int KT   = 64;            // K per smem tile (halfs) = 128B rows
constexpr int NFC  = En / NT;       // 4 f-chunks
constexpr int NKT  = En / KT;       // 16 k-tiles per f-chunk
constexpr int TILES = NFC * NKT;    // 64
constexpr int NTHR = 384;           // 12 warps: 3 (M, 32 rows) x 4 (N, 64 cols)
constexpr int WMN  = 3;
constexpr int WNN  = 4;

constexpr int A_TILE_B = MT * KT * 2;   // 12288 bytes
constexpr int B_TILE_B = NT * KT * 2;   // 32768 bytes
constexpr int OFF_A  = 0;
constexpr int OFF_B  = OFF_A + 2 * A_TILE_B;     // 24576
constexpr int OFF_U  = OFF_B + 2 * B_TILE_B;     // 90112
constexpr int OFF_SP = OFF_U + En * 4;           // 94208
constexpr int SMEM_TOTAL = OFF_SP + MT * WNN * 4; // 95744 bytes

__device__ float g_attn[Bn * Sn];

// ---------------------------------------------------------------------------
__device__ __forceinline__ uint32_t cvt2(float a, float b) {
    __half2 h = __floats2half2_rn(a, b);   // low = a (even k), high = b
    return *reinterpret_cast<uint32_t*>(&h);
}

__device__ __forceinline__ void ldsm4(uint32_t& r0, uint32_t& r1,
                                      uint32_t& r2, uint32_t& r3, uint32_t addr) {
    asm volatile("ldmatrix.sync.aligned.m8n8.x4.shared.b16 {%0,%1,%2,%3}, [%4];"
                 : "=r"(r0), "=r"(r1), "=r"(r2), "=r"(r3) : "r"(addr));
}

__device__ __forceinline__ void mma16816(float* c,
                                         uint32_t a0, uint32_t a1, uint32_t a2, uint32_t a3,
                                         uint32_t b0, uint32_t b1) {
    asm volatile(
        "mma.sync.aligned.m16n8k16.row.col.f32.f16.f16.f32 "
        "{%0,%1,%2,%3},{%4,%5,%6,%7},{%8,%9},{%0,%1,%2,%3};"
        : "+f"(c[0]), "+f"(c[1]), "+f"(c[2]), "+f"(c[3])
        : "r"(a0), "r"(a1), "r"(a2), "r"(a3), "r"(b0), "r"(b1));
}

// ---------------------------------------------------------------------------
// Kernel A: fused scores + softmax per batch, fp16 tensor-core pipeline.
// ---------------------------------------------------------------------------
extern __shared__ char smem[];

__global__ __launch_bounds__(NTHR, 1)
void scores_kernel(const float* __restrict__ x,
                   const float* __restrict__ W,
                   const float* __restrict__ u,
                   const int* __restrict__ doc) {
    const int b    = blockIdx.x;
    const int tid  = threadIdx.x;
    const int lane = tid & 31;
    const int wid  = tid >> 5;
    const int wm   = wid % WMN;       // M-warp: rows [wm*32, wm*32+32)
    const int wn   = wid / WMN;       // N-warp: cols [wn*64, wn*64+64)
    const int g    = lane >> 2;
    const int tg   = lane & 3;

    const int start = doc[2 * b];
    const int len   = doc[2 * b + 1] - start;    // 1..96
    const int nmt   = (len + 15) >> 4;           // active 16-row subtiles
    int nms = nmt - wm * 2;                       // this warp's active subtiles
    nms = nms < 0 ? 0 : (nms > 2 ? 2 : nms);

    const uint32_t smem_u32 = (uint32_t)__cvta_generic_to_shared(smem);
    float* u_s    = reinterpret_cast<float*>(smem + OFF_U);
    float* s_part = reinterpret_cast<float*>(smem + OFF_SP);

    for (int i = tid; i < En; i += NTHR) u_s[i] = u[i];
    for (int i = tid; i < MT * WNN; i += NTHR) s_part[i] = 0.0f;

    // staging regs (half2-packed): A 2 chunks, B 6 chunks of 16B each
    uint32_t sa[2][4];
    uint32_t sb[6][4];

    auto load_stage = [&](int t) {
        const int fc = t >> 4;
        const int k0 = (t & 15) * KT;
        #pragma unroll
        for (int i = 0; i < 2; i++) {
            int ch = tid + i * NTHR;            // 768 A chunks
            int m = ch >> 3, c = ch & 7;
            float4 v0 = make_float4(0.f, 0.f, 0.f, 0.f);
            float4 v1 = make_float4(0.f, 0.f, 0.f, 0.f);
            if (m < len) {
                const float4* p = reinterpret_cast<const float4*>(
                    x + (size_t)(b * Sn + start + m) * En + k0 + c * 8);
                v0 = p[0]; v1 = p[1];
            }
            sa[i][0] = cvt2(v0.x, v0.y); sa[i][1] = cvt2(v0.z, v0.w);
            sa[i][2] = cvt2(v1.x, v1.y); sa[i][3] = cvt2(v1.z, v1.w);
        }
        #pragma unroll
        for (int i = 0; i < 6; i++) {
            int ch = tid + i * NTHR;            // 2048 B chunks
            if (ch < NT * 8) {
                int n = ch >> 3, c = ch & 7;
                const float4* p = reinterpret_cast<const float4*>(
                    W + (size_t)(fc * NT + n) * En + k0 + c * 8);
                float4 v0 = p[0], v1 = p[1];
                sb[i][0] = cvt2(v0.x, v0.y); sb[i][1] = cvt2(v0.z, v0.w);
                sb[i][2] = cvt2(v1.x, v1.y); sb[i][3] = cvt2(v1.z, v1.w);
            }
        }
    };

    auto sts_stage = [&](int buf) {
        #pragma unroll
        for (int i = 0; i < 2; i++) {
            int ch = tid + i * NTHR;
            int m = ch >> 3, c = ch & 7;
            uint4* dst = reinterpret_cast<uint4*>(
                smem + OFF_A + buf * A_TILE_B + m * 128 + ((c ^ (m & 7)) * 16));
            *dst = make_uint4(sa[i][0], sa[i][1], sa[i][2], sa[i][3]);
        }
        #pragma unroll
        for (int i = 0; i < 6; i++) {
            int ch = tid + i * NTHR;
            if (ch < NT * 8) {
                int n = ch >> 3, c = ch & 7;
                uint4* dst = reinterpret_cast<uint4*>(
                    smem + OFF_B + buf * B_TILE_B + n * 128 + ((c ^ (n & 7)) * 16));
                *dst = make_uint4(sb[i][0], sb[i][1], sb[i][2], sb[i][3]);
            }
        }
    };

    float acc[2][8][4];
    #pragma unroll
    for (int ms = 0; ms < 2; ms++)
        #pragma unroll
        for (int j = 0; j < 8; j++)
            #pragma unroll
            for (int i = 0; i < 4; i++) acc[ms][j][i] = 0.0f;
    float sacc[2][2] = {{0.f, 0.f}, {0.f, 0.f}};

    // prologue
    load_stage(0);
    sts_stage(0);
    __syncthreads();
    load_stage(1);

    // ldmatrix lane-address components (constant across tiles)
    const int a_row   = (lane & 15);             // + subtile base
    const int a_choff = (lane >> 4);             // 0/1 -> +8 halfs
    const int b_rowin = (lane & 7) + ((lane >> 4) << 3);
    const int b_choff = ((lane >> 3) & 1);

    for (int t = 0; t < TILES; t++) {
        if (t + 1 < TILES) sts_stage((t + 1) & 1);
        if (t + 2 < TILES) load_stage(t + 2);

        const int buf = t & 1;
        const uint32_t aBase = smem_u32 + OFF_A + buf * A_TILE_B;
        const uint32_t bBase = smem_u32 + OFF_B + buf * B_TILE_B;

        if (nms > 0) {
            #pragma unroll
            for (int ks = 0; ks < 4; ks++) {
                uint32_t af[2][4];
                #pragma unroll
                for (int ms = 0; ms < 2; ms++) {
                    if (ms < nms) {
                        int row = wm * 32 + ms * 16 + a_row;
                        int chv = 2 * ks + a_choff;
                        uint32_t addr = aBase + row * 128 + ((chv ^ (row & 7)) * 16);
                        ldsm4(af[ms][0], af[ms][1], af[ms][2], af[ms][3], addr);
                    }
                }
                uint32_t bf[4][4];
                #pragma unroll
                for (int jp = 0; jp < 4; jp++) {
                    int nrow = wn * 64 + jp * 16 + b_rowin;
                    int chv = 2 * ks + b_choff;
                    uint32_t addr = bBase + nrow * 128 + ((chv ^ (nrow & 7)) * 16);
                    ldsm4(bf[jp][0], bf[jp][1], bf[jp][2], bf[jp][3], addr);
                }
                #pragma unroll
                for (int ms = 0; ms < 2; ms++) {
                    if (ms < nms) {
                        #pragma unroll
                        for (int j = 0; j < 8; j++) {
                            mma16816(acc[ms][j],
                                     af[ms][0], af[ms][1], af[ms][2], af[ms][3],
                                     bf[j >> 1][(j & 1) * 2], bf[j >> 1][(j & 1) * 2 + 1]);
                        }
                    }
                }
            }
        }

        if ((t & 15) == 15) {
            // f-chunk epilogue: scores += tanh(z) * u
            const int fc = t >> 4;
            #pragma unroll
            for (int ms = 0; ms < 2; ms++) {
                if (ms < nms) {
                    #pragma unroll
                    for (int j = 0; j < 8; j++) {
                        int f = fc * NT + wn * 64 + j * 8 + 2 * tg;
                        float u0 = u_s[f], u1 = u_s[f + 1];
                        sacc[ms][0] += tanhf(acc[ms][j][0]) * u0 + tanhf(acc[ms][j][1]) * u1;
                        sacc[ms][1] += tanhf(acc[ms][j][2]) * u0 + tanhf(acc[ms][j][3]) * u1;
                        acc[ms][j][0] = 0.f; acc[ms][j][1] = 0.f;
                        acc[ms][j][2] = 0.f; acc[ms][j][3] = 0.f;
                    }
                }
            }
        }
        __syncthreads();
    }

    // reduce over tg (deterministic shuffles), write partials
    #pragma unroll
    for (int ms = 0; ms < 2; ms++) {
        #pragma unroll
        for (int rg = 0; rg < 2; rg++) {
            float v = sacc[ms][rg];
            v += __shfl_xor_sync(0xffffffffu, v, 1);
            v += __shfl_xor_sync(0xffffffffu, v, 2);
            if (ms < nms && tg == 0) {
                int row = wm * 32 + ms * 16 + rg * 8 + g;
                s_part[row * WNN + wn] = v;
            }
        }
    }
    __syncthreads();

    // softmax over the bag — warp 0 (deterministic)
    if (wid == 0) {
        float v[3];
        #pragma unroll
        for (int i = 0; i < 3; i++) {
            int r = lane + 32 * i;
            float sv = s_part[r * WNN + 0] + s_part[r * WNN + 1] +
                       s_part[r * WNN + 2] + s_part[r * WNN + 3];
            v[i] = (r < len) ? sv : -3.0e38f;
        }
        float mx = fmaxf(v[0], fmaxf(v[1], v[2]));
        #pragma unroll
        for (int o = 16; o > 0; o >>= 1)
            mx = fmaxf(mx, __shfl_xor_sync(0xffffffffu, mx, o));
        float e[3];
        float ssum = 0.0f;
        #pragma unroll
        for (int i = 0; i < 3; i++) {
            int r = lane + 32 * i;
            e[i] = (r < len) ? __expf(v[i] - mx) : 0.0f;
            ssum += e[i];
        }
        #pragma unroll
        for (int o = 16; o > 0; o >>= 1)
            ssum += __shfl_xor_sync(0xffffffffu, ssum, o);
        float inv = 1.0f / ssum;
        #pragma unroll
        for (int i = 0; i < 3; i++) {
            int r = lane + 32 * i;
            if (r < len) g_attn[b * Sn + start + r] = e[i] * inv;
        }
    }
}

// ---------------------------------------------------------------------------
// Kernel B: out_concat[b,:] = sum_s attn[b,s] * x[b,s,:]
// ---------------------------------------------------------------------------
__global__ __launch_bounds__(256)
void out_kernel(const float4* __restrict__ x4,
                const int* __restrict__ doc,
                float* __restrict__ out) {
    const int b = blockIdx.x;
    const int t = threadIdx.x;
    const int start = doc[2 * b];
    const int end   = doc[2 * b + 1];
    float4 acc = make_float4(0.f, 0.f, 0.f, 0.f);
    for (int s = start; s < end; s++) {
        float a = g_attn[b * Sn + s];
        float4 xv = x4[(size_t)(b * Sn + s) * (En / 4) + t];
        acc.x += a * xv.x;
        acc.y += a * xv.y;
        acc.z += a * xv.z;
        acc.w += a * xv.w;
    }
    reinterpret_cast<float4*>(out)[(size_t)b * (En / 4) + t] = acc;
}

// ---------------------------------------------------------------------------
// Kernel C: keep_attention = attn[B-1] (zeros outside the bag)
// ---------------------------------------------------------------------------
__global__ void keep_kernel(const int* __restrict__ doc, float* __restrict__ out) {
    const int s = threadIdx.x;
    const int b = Bn - 1;
    const int start = doc[2 * b];
    const int end   = doc[2 * b + 1];
    out[(size_t)Bn * En + s] = (s >= start && s < end) ? g_attn[b * Sn + s] : 0.0f;
}

// ---------------------------------------------------------------------------
extern "C" void kernel_launch(void* const* d_in, const int* in_sizes, int n_in,
                              void* d_out, int out_size) {
    const float* x   = (const float*)d_in[0];
    const float* W   = (const float*)d_in[1];
    const float* u   = (const float*)d_in[2];
    const int*   doc = (const int*)d_in[3];
    float* out = (float*)d_out;

    cudaFuncSetAttribute(scores_kernel,
                         cudaFuncAttributeMaxDynamicSharedMemorySize, SMEM_TOTAL);
    scores_kernel<<<Bn, NTHR, SMEM_TOTAL>>>(x, W, u, doc);
    out_kernel<<<Bn, 256>>>((const float4*)x, doc, out);
    keep_kernel<<<1, Sn>>>(doc, out);
}

// round 3
// speedup vs baseline: 2.7402x; 1.3161x over previous
#include <cuda_runtime.h>
#include <cuda_fp16.h>
#include <cstdint>
#include <cstddef>

#define Bn 256
#define Sn 128
#define En 1024

constexpr int MT   = 96;
constexpr int NT   = 128;           // f-columns per chunk
constexpr int KT   = 64;            // K halfs per tile (128B rows)
constexpr int NFC  = En / NT;       // 8
constexpr int NKT  = En / KT;       // 16
constexpr int TILES = NFC * NKT;    // 128
constexpr int NTHR = 256;           // 8 warps: 2 (M: 48 rows) x 4 (N: 32 cols)
constexpr int WMN  = 2;
constexpr int WNN  = 4;
constexpr int STAGES = 3;

constexpr int A_TILE_B = MT * KT * 2;   // 12288
constexpr int B_TILE_B = NT * KT * 2;   // 16384
constexpr int STG_B    = A_TILE_B + B_TILE_B;          // 28672
constexpr int OFF_U    = STAGES * STG_B;               // 86016
constexpr int OFF_SP   = OFF_U + En * 4;               // 90112
constexpr int SMEM_TOTAL = OFF_SP + MT * WNN * 4;      // 91648

// device-global scratch (allocations are forbidden)
__device__ float  g_attn[Bn * Sn];
__device__ __half g_Wh[En * En];
__device__ __half g_xh[Bn * Sn * En];

// ---------------------------------------------------------------------------
__device__ __forceinline__ void cp16(uint32_t dst, const void* src, bool pred) {
    int sz = pred ? 16 : 0;
    asm volatile("cp.async.cg.shared.global [%0], [%1], 16, %2;\n"
                 :: "r"(dst), "l"(src), "r"(sz));
}
__device__ __forceinline__ void cp_commit() {
    asm volatile("cp.async.commit_group;\n");
}
__device__ __forceinline__ void cp_wait1() {
    asm volatile("cp.async.wait_group 1;\n");
}

__device__ __forceinline__ void ldsm4(uint32_t& r0, uint32_t& r1,
                                      uint32_t& r2, uint32_t& r3, uint32_t addr) {
    asm volatile("ldmatrix.sync.aligned.m8n8.x4.shared.b16 {%0,%1,%2,%3}, [%4];"
                 : "=r"(r0), "=r"(r1), "=r"(r2), "=r"(r3) : "r"(addr));
}

__device__ __forceinline__ void mma16816(float* c,
                                         uint32_t a0, uint32_t a1, uint32_t a2, uint32_t a3,
                                         uint32_t b0, uint32_t b1) {
    asm volatile(
        "mma.sync.aligned.m16n8k16.row.col.f32.f16.f16.f32 "
        "{%0,%1,%2,%3},{%4,%5,%6,%7},{%8,%9},{%0,%1,%2,%3};"
        : "+f"(c[0]), "+f"(c[1]), "+f"(c[2]), "+f"(c[3])
        : "r"(a0), "r"(a1), "r"(a2), "r"(a3), "r"(b0), "r"(b1));
}

// ---------------------------------------------------------------------------
// Pre-convert kernels (fp32 -> fp16)
// ---------------------------------------------------------------------------
__global__ __launch_bounds__(256)
void convW_kernel(const float4* __restrict__ W4) {
    int idx = blockIdx.x * 256 + threadIdx.x;       // 262144 float4s
    float4 v = W4[idx];
    __half2* o = reinterpret_cast<__half2*>(g_Wh);
    o[idx * 2]     = __floats2half2_rn(v.x, v.y);
    o[idx * 2 + 1] = __floats2half2_rn(v.z, v.w);
}

__global__ __launch_bounds__(256)
void convX_kernel(const float4* __restrict__ x4, const int* __restrict__ doc) {
    const int b = blockIdx.x;
    const int start = doc[2 * b];
    const int end   = doc[2 * b + 1];
    const int t = threadIdx.x;
    __half2* o = reinterpret_cast<__half2*>(g_xh);
    for (int s = start; s < end; s++) {
        size_t base = (size_t)(b * Sn + s) * (En / 4) + t;
        float4 v = x4[base];
        o[base * 2]     = __floats2half2_rn(v.x, v.y);
        o[base * 2 + 1] = __floats2half2_rn(v.z, v.w);
    }
}

// ---------------------------------------------------------------------------
// Kernel A: fused scores + softmax, cp.async fp16 tensor-core pipeline.
// ---------------------------------------------------------------------------
extern __shared__ char smem[];

__global__ __launch_bounds__(NTHR, 2)
void scores_kernel(const float* __restrict__ u,
                   const int* __restrict__ doc) {
    const int b    = blockIdx.x;
    const int tid  = threadIdx.x;
    const int lane = tid & 31;
    const int wid  = tid >> 5;
    const int wm   = wid % WMN;       // rows [wm*48, wm*48+48)
    const int wn   = wid / WMN;       // cols [wn*32, wn*32+32)
    const int g    = lane >> 2;
    const int tg   = lane & 3;

    const int start = doc[2 * b];
    const int len   = doc[2 * b + 1] - start;    // 1..96
    const int nmt   = (len + 15) >> 4;           // active 16-row subtiles (1..6)
    int nms = nmt - wm * 3;
    nms = nms < 0 ? 0 : (nms > 3 ? 3 : nms);

    const uint32_t smem_u32 = (uint32_t)__cvta_generic_to_shared(smem);
    float* u_s    = reinterpret_cast<float*>(smem + OFF_U);
    float* s_part = reinterpret_cast<float*>(smem + OFF_SP);

    for (int i = tid; i < En; i += NTHR) u_s[i] = u[i];
    for (int i = tid; i < MT * WNN; i += NTHR) s_part[i] = 0.0f;

    // fill-lane constants
    const int fa_m = tid >> 3;            // A chunk base: m for i=0 (m = (tid+i*256)>>3)
    const int fa_c = tid & 7;

    auto fill = [&](int t, int buf) {
        const int fc = t >> 4;
        const int k0 = (t & 15) * KT;
        const uint32_t aBase = smem_u32 + buf * STG_B;
        const uint32_t bBase = aBase + A_TILE_B;
        #pragma unroll
        for (int i = 0; i < 3; i++) {           // 768 A chunks / 256 thr
            int m = fa_m + i * 32;
            uint32_t dst = aBase + m * 128 + ((fa_c ^ (m & 7)) << 4);
            const __half* src = g_xh + (size_t)(b * Sn + start + m) * En + k0 + fa_c * 8;
            cp16(dst, src, m < len);
        }
        #pragma unroll
        for (int i = 0; i < 4; i++) {           // 1024 B chunks / 256 thr
            int n = fa_m + i * 32;
            uint32_t dst = bBase + n * 128 + ((fa_c ^ (n & 7)) << 4);
            const __half* src = g_Wh + (size_t)(fc * NT + n) * En + k0 + fa_c * 8;
            cp16(dst, src, true);
        }
        cp_commit();
    };

    float acc[3][4][4];
    #pragma unroll
    for (int ms = 0; ms < 3; ms++)
        #pragma unroll
        for (int j = 0; j < 4; j++)
            #pragma unroll
            for (int i = 0; i < 4; i++) acc[ms][j][i] = 0.0f;
    float sacc[3][2] = {{0.f,0.f},{0.f,0.f},{0.f,0.f}};

    // ldmatrix lane-address components
    const int a_row   = (lane & 15);
    const int a_choff = (lane >> 4);
    const int b_rowin = (lane & 7) + ((lane >> 4) << 3);
    const int b_choff = ((lane >> 3) & 1);

    // prologue: stage tiles 0 and 1
    fill(0, 0);
    fill(1, 1);

    for (int t = 0; t < TILES; t++) {
        cp_wait1();          // tile t landed (<=1 group pending)
        __syncthreads();     // visibility + everyone done reading buf (t-1)%3
        if (t + 2 < TILES) fill(t + 2, (t + 2) % STAGES);
        else cp_commit();    // keep group count uniform

        const uint32_t aBase = smem_u32 + (t % STAGES) * STG_B;
        const uint32_t bBase = aBase + A_TILE_B;

        if (nms > 0) {
            #pragma unroll
            for (int ks = 0; ks < 4; ks++) {
                uint32_t af[3][4];
                #pragma unroll
                for (int ms = 0; ms < 3; ms++) {
                    if (ms < nms) {
                        int row = wm * 48 + ms * 16 + a_row;
                        int chv = 2 * ks + a_choff;
                        uint32_t addr = aBase + row * 128 + ((chv ^ (row & 7)) << 4);
                        ldsm4(af[ms][0], af[ms][1], af[ms][2], af[ms][3], addr);
                    }
                }
                uint32_t bf[2][4];
                #pragma unroll
                for (int jp = 0; jp < 2; jp++) {
                    int nrow = wn * 32 + jp * 16 + b_rowin;
                    int chv = 2 * ks + b_choff;
                    uint32_t addr = bBase + nrow * 128 + ((chv ^ (nrow & 7)) << 4);
                    ldsm4(bf[jp][0], bf[jp][1], bf[jp][2], bf[jp][3], addr);
                }
                #pragma unroll
                for (int ms = 0; ms < 3; ms++) {
                    if (ms < nms) {
                        #pragma unroll
                        for (int j = 0; j < 4; j++) {
                            mma16816(acc[ms][j],
                                     af[ms][0], af[ms][1], af[ms][2], af[ms][3],
                                     bf[j >> 1][(j & 1) * 2], bf[j >> 1][(j & 1) * 2 + 1]);
                        }
                    }
                }
            }
        }

        if ((t & 15) == 15) {
            const int fc = t >> 4;
            #pragma unroll
            for (int ms = 0; ms < 3; ms++) {
                if (ms < nms) {
                    #pragma unroll
                    for (int j = 0; j < 4; j++) {
                        int f = fc * NT + wn * 32 + j * 8 + 2 * tg;
                        float u0 = u_s[f], u1 = u_s[f + 1];
                        sacc[ms][0] += tanhf(acc[ms][j][0]) * u0 + tanhf(acc[ms][j][1]) * u1;
                        sacc[ms][1] += tanhf(acc[ms][j][2]) * u0 + tanhf(acc[ms][j][3]) * u1;
                        acc[ms][j][0] = 0.f; acc[ms][j][1] = 0.f;
                        acc[ms][j][2] = 0.f; acc[ms][j][3] = 0.f;
                    }
                }
            }
        }
    }

    // deterministic tg-reduction, write partials
    #pragma unroll
    for (int ms = 0; ms < 3; ms++) {
        #pragma unroll
        for (int rg = 0; rg < 2; rg++) {
            float v = sacc[ms][rg];
            v += __shfl_xor_sync(0xffffffffu, v, 1);
            v += __shfl_xor_sync(0xffffffffu, v, 2);
            if (ms < nms && tg == 0) {
                int row = wm * 48 + ms * 16 + rg * 8 + g;
                s_part[row * WNN + wn] = v;
            }
        }
    }
    __syncthreads();

    // softmax over the bag — warp 0 (deterministic)
    if (wid == 0) {
        float v[3];
        #pragma unroll
        for (int i = 0; i < 3; i++) {
            int r = lane + 32 * i;
            float sv = s_part[r * WNN + 0] + s_part[r * WNN + 1] +
                       s_part[r * WNN + 2] + s_part[r * WNN + 3];
            v[i] = (r < len) ? sv : -3.0e38f;
        }
        float mx = fmaxf(v[0], fmaxf(v[1], v[2]));
        #pragma unroll
        for (int o = 16; o > 0; o >>= 1)
            mx = fmaxf(mx, __shfl_xor_sync(0xffffffffu, mx, o));
        float e[3];
        float ssum = 0.0f;
        #pragma unroll
        for (int i = 0; i < 3; i++) {
            int r = lane + 32 * i;
            e[i] = (r < len) ? __expf(v[i] - mx) : 0.0f;
            ssum += e[i];
        }
        #pragma unroll
        for (int o = 16; o > 0; o >>= 1)
            ssum += __shfl_xor_sync(0xffffffffu, ssum, o);
        float inv = 1.0f / ssum;
        #pragma unroll
        for (int i = 0; i < 3; i++) {
            int r = lane + 32 * i;
            if (r < len) g_attn[b * Sn + start + r] = e[i] * inv;
        }
    }
}

// ---------------------------------------------------------------------------
// Kernel B: out_concat[b,:] = sum_s attn[b,s] * x[b,s,:]   (fp32 x, exact)
// ---------------------------------------------------------------------------
__global__ __launch_bounds__(256)
void out_kernel(const float4* __restrict__ x4,
                const int* __restrict__ doc,
                float* __restrict__ out) {
    const int b = blockIdx.x;
    const int t = threadIdx.x;
    const int start = doc[2 * b];
    const int end   = doc[2 * b + 1];
    float4 acc = make_float4(0.f, 0.f, 0.f, 0.f);
    for (int s = start; s < end; s++) {
        float a = g_attn[b * Sn + s];
        float4 xv = x4[(size_t)(b * Sn + s) * (En / 4) + t];
        acc.x += a * xv.x;
        acc.y += a * xv.y;
        acc.z += a * xv.z;
        acc.w += a * xv.w;
    }
    reinterpret_cast<float4*>(out)[(size_t)b * (En / 4) + t] = acc;
}

__global__ void keep_kernel(const int* __restrict__ doc, float* __restrict__ out) {
    const int s = threadIdx.x;
    const int b = Bn - 1;
    const int start = doc[2 * b];
    const int end   = doc[2 * b + 1];
    out[(size_t)Bn * En + s] = (s >= start && s < end) ? g_attn[b * Sn + s] : 0.0f;
}

// ---------------------------------------------------------------------------
extern "C" void kernel_launch(void* const* d_in, const int* in_sizes, int n_in,
                              void* d_out, int out_size) {
    const float* x   = (const float*)d_in[0];
    const float* W   = (const float*)d_in[1];
    const float* u   = (const float*)d_in[2];
    const int*   doc = (const int*)d_in[3];
    float* out = (float*)d_out;

    convW_kernel<<<1024, 256>>>((const float4*)W);
    convX_kernel<<<Bn, 256>>>((const float4*)x, doc);

    cudaFuncSetAttribute(scores_kernel,
                         cudaFuncAttributeMaxDynamicSharedMemorySize, SMEM_TOTAL);
    scores_kernel<<<Bn, NTHR, SMEM_TOTAL>>>(u, doc);

    out_kernel<<<Bn, 256>>>((const float4*)x, doc, out);
    keep_kernel<<<1, Sn>>>(doc, out);
}

// round 4
// speedup vs baseline: 2.9580x; 1.0795x over previous
#include <cuda_runtime.h>
#include <cuda_fp16.h>
#include <cstdint>
#include <cstddef>

#define Bn 256
#define Sn 128
#define En 1024

constexpr int MT   = 96;
constexpr int NT   = 128;           // f-columns per chunk
constexpr int KT   = 64;            // K halfs per tile (128B rows)
constexpr int NFC  = En / NT;       // 8
constexpr int NKT  = En / KT;       // 16
constexpr int TILES = NFC * NKT;    // 128
constexpr int NTHR = 256;           // 8 warps: 2 (M, interleaved subtiles) x 4 (N, 32 cols)
constexpr int WMN  = 2;
constexpr int WNN  = 4;
constexpr int STAGES = 3;

constexpr int A_TILE_B = MT * KT * 2;   // 12288
constexpr int B_TILE_B = NT * KT * 2;   // 16384
constexpr int STG_B    = A_TILE_B + B_TILE_B;          // 28672
constexpr int OFF_U    = STAGES * STG_B;               // 86016
constexpr int OFF_SP   = OFF_U + En * 4;               // 90112
constexpr int OFF_AT   = OFF_SP + MT * WNN * 4;        // 91648
constexpr int SMEM_TOTAL = OFF_AT + MT * 4;            // 92032

// device-global scratch (allocations are forbidden)
__device__ __half g_Wh[En * En];
__device__ __half g_xh[Bn * Sn * En];

// ---------------------------------------------------------------------------
__device__ __forceinline__ void cp16(uint32_t dst, const void* src, bool pred) {
    int sz = pred ? 16 : 0;
    asm volatile("cp.async.cg.shared.global [%0], [%1], 16, %2;\n"
                 :: "r"(dst), "l"(src), "r"(sz));
}
__device__ __forceinline__ void cp_commit() {
    asm volatile("cp.async.commit_group;\n");
}
__device__ __forceinline__ void cp_wait1() {
    asm volatile("cp.async.wait_group 1;\n");
}

__device__ __forceinline__ void ldsm4(uint32_t& r0, uint32_t& r1,
                                      uint32_t& r2, uint32_t& r3, uint32_t addr) {
    asm volatile("ldmatrix.sync.aligned.m8n8.x4.shared.b16 {%0,%1,%2,%3}, [%4];"
                 : "=r"(r0), "=r"(r1), "=r"(r2), "=r"(r3) : "r"(addr));
}

__device__ __forceinline__ void mma16816(float* c,
                                         uint32_t a0, uint32_t a1, uint32_t a2, uint32_t a3,
                                         uint32_t b0, uint32_t b1) {
    asm volatile(
        "mma.sync.aligned.m16n8k16.row.col.f32.f16.f16.f32 "
        "{%0,%1,%2,%3},{%4,%5,%6,%7},{%8,%9},{%0,%1,%2,%3};"
        : "+f"(c[0]), "+f"(c[1]), "+f"(c[2]), "+f"(c[3])
        : "r"(a0), "r"(a1), "r"(a2), "r"(a3), "r"(b0), "r"(b1));
}

// ---------------------------------------------------------------------------
// Pre-convert kernels (fp32 -> fp16)
// ---------------------------------------------------------------------------
__global__ __launch_bounds__(256)
void convW_kernel(const float4* __restrict__ W4) {
    int idx = blockIdx.x * 256 + threadIdx.x;       // 262144 float4s
    float4 v = W4[idx];
    __half2* o = reinterpret_cast<__half2*>(g_Wh);
    o[idx * 2]     = __floats2half2_rn(v.x, v.y);
    o[idx * 2 + 1] = __floats2half2_rn(v.z, v.w);
}

__global__ __launch_bounds__(256)
void convX_kernel(const float4* __restrict__ x4, const int* __restrict__ doc) {
    const int b = blockIdx.x;
    const int start = doc[2 * b];
    const int end   = doc[2 * b + 1];
    const int t = threadIdx.x;
    __half2* o = reinterpret_cast<__half2*>(g_xh);
    for (int s = start; s < end; s++) {
        size_t base = (size_t)(b * Sn + s) * (En / 4) + t;
        float4 v = x4[base];
        o[base * 2]     = __floats2half2_rn(v.x, v.y);
        o[base * 2 + 1] = __floats2half2_rn(v.z, v.w);
    }
}

// ---------------------------------------------------------------------------
// Kernel A: fused scores + softmax + out GEMV + keep_attention.
// ---------------------------------------------------------------------------
extern __shared__ char smem[];

__global__ __launch_bounds__(NTHR, 2)
void scores_kernel(const float4* __restrict__ x4,
                   const float* __restrict__ u,
                   const int* __restrict__ doc,
                   float* __restrict__ out) {
    const int b    = blockIdx.x;
    const int tid  = threadIdx.x;
    const int lane = tid & 31;
    const int wid  = tid >> 5;
    const int wm   = wid % WMN;       // subtiles st with st%2==wm (interleaved)
    const int wn   = wid / WMN;       // cols [wn*32, wn*32+32)
    const int g    = lane >> 2;
    const int tg   = lane & 3;

    const int start = doc[2 * b];
    const int len   = doc[2 * b + 1] - start;    // 1..96
    const int nmt   = (len + 15) >> 4;           // active 16-row subtiles (1..6)
    const int nms   = (nmt + 1 - wm) >> 1;       // this warp's active subtiles (0..3)

    const uint32_t smem_u32 = (uint32_t)__cvta_generic_to_shared(smem);
    float* u_s    = reinterpret_cast<float*>(smem + OFF_U);
    float* s_part = reinterpret_cast<float*>(smem + OFF_SP);
    float* attn_s = reinterpret_cast<float*>(smem + OFF_AT);

    for (int i = tid; i < En; i += NTHR) u_s[i] = u[i];
    for (int i = tid; i < MT * WNN; i += NTHR) s_part[i] = 0.0f;

    // fill-lane constants
    const int fa_m = tid >> 3;
    const int fa_c = tid & 7;

    auto fill = [&](int t, int buf) {
        const int fc = t >> 4;
        const int k0 = (t & 15) * KT;
        const uint32_t aBase = smem_u32 + buf * STG_B;
        const uint32_t bBase = aBase + A_TILE_B;
        #pragma unroll
        for (int i = 0; i < 3; i++) {           // 768 A chunks / 256 thr
            int m = fa_m + i * 32;
            uint32_t dst = aBase + m * 128 + ((fa_c ^ (m & 7)) << 4);
            const __half* src = g_xh + (size_t)(b * Sn + start + m) * En + k0 + fa_c * 8;
            cp16(dst, src, m < len);
        }
        #pragma unroll
        for (int i = 0; i < 4; i++) {           // 1024 B chunks / 256 thr
            int n = fa_m + i * 32;
            uint32_t dst = bBase + n * 128 + ((fa_c ^ (n & 7)) << 4);
            const __half* src = g_Wh + (size_t)(fc * NT + n) * En + k0 + fa_c * 8;
            cp16(dst, src, true);
        }
        cp_commit();
    };

    float acc[3][4][4];
    #pragma unroll
    for (int ms = 0; ms < 3; ms++)
        #pragma unroll
        for (int j = 0; j < 4; j++)
            #pragma unroll
            for (int i = 0; i < 4; i++) acc[ms][j][i] = 0.0f;
    float sacc[3][2] = {{0.f,0.f},{0.f,0.f},{0.f,0.f}};

    // ldmatrix lane-address components
    const int a_row   = (lane & 15);
    const int a_choff = (lane >> 4);
    const int b_rowin = (lane & 7) + ((lane >> 4) << 3);
    const int b_choff = ((lane >> 3) & 1);

    // prologue: stage tiles 0 and 1
    fill(0, 0);
    fill(1, 1);

    for (int t = 0; t < TILES; t++) {
        cp_wait1();
        __syncthreads();
        if (t + 2 < TILES) fill(t + 2, (t + 2) % STAGES);
        else cp_commit();    // keep group count uniform

        const uint32_t aBase = smem_u32 + (t % STAGES) * STG_B;
        const uint32_t bBase = aBase + A_TILE_B;

        if (nms > 0) {
            #pragma unroll
            for (int ks = 0; ks < 4; ks++) {
                uint32_t af[3][4];
                #pragma unroll
                for (int ms = 0; ms < 3; ms++) {
                    if (ms < nms) {
                        int row = (2 * ms + wm) * 16 + a_row;   // interleaved subtile
                        int chv = 2 * ks + a_choff;
                        uint32_t addr = aBase + row * 128 + ((chv ^ (row & 7)) << 4);
                        ldsm4(af[ms][0], af[ms][1], af[ms][2], af[ms][3], addr);
                    }
                }
                uint32_t bf[2][4];
                #pragma unroll
                for (int jp = 0; jp < 2; jp++) {
                    int nrow = wn * 32 + jp * 16 + b_rowin;
                    int chv = 2 * ks + b_choff;
                    uint32_t addr = bBase + nrow * 128 + ((chv ^ (nrow & 7)) << 4);
                    ldsm4(bf[jp][0], bf[jp][1], bf[jp][2], bf[jp][3], addr);
                }
                #pragma unroll
                for (int ms = 0; ms < 3; ms++) {
                    if (ms < nms) {
                        #pragma unroll
                        for (int j = 0; j < 4; j++) {
                            mma16816(acc[ms][j],
                                     af[ms][0], af[ms][1], af[ms][2], af[ms][3],
                                     bf[j >> 1][(j & 1) * 2], bf[j >> 1][(j & 1) * 2 + 1]);
                        }
                    }
                }
            }
        }

        if ((t & 15) == 15) {
            const int fc = t >> 4;
            #pragma unroll
            for (int ms = 0; ms < 3; ms++) {
                if (ms < nms) {
                    #pragma unroll
                    for (int j = 0; j < 4; j++) {
                        int f = fc * NT + wn * 32 + j * 8 + 2 * tg;
                        float u0 = u_s[f], u1 = u_s[f + 1];
                        sacc[ms][0] += tanhf(acc[ms][j][0]) * u0 + tanhf(acc[ms][j][1]) * u1;
                        sacc[ms][1] += tanhf(acc[ms][j][2]) * u0 + tanhf(acc[ms][j][3]) * u1;
                        acc[ms][j][0] = 0.f; acc[ms][j][1] = 0.f;
                        acc[ms][j][2] = 0.f; acc[ms][j][3] = 0.f;
                    }
                }
            }
        }
    }

    // deterministic tg-reduction, write partials
    #pragma unroll
    for (int ms = 0; ms < 3; ms++) {
        #pragma unroll
        for (int rg = 0; rg < 2; rg++) {
            float v = sacc[ms][rg];
            v += __shfl_xor_sync(0xffffffffu, v, 1);
            v += __shfl_xor_sync(0xffffffffu, v, 2);
            if (ms < nms && tg == 0) {
                int row = (2 * ms + wm) * 16 + rg * 8 + g;
                s_part[row * WNN + wn] = v;
            }
        }
    }
    __syncthreads();

    // softmax over the bag — warp 0 (deterministic); result -> attn_s[0..95]
    if (wid == 0) {
        float v[3];
        #pragma unroll
        for (int i = 0; i < 3; i++) {
            int r = lane + 32 * i;
            float sv = s_part[r * WNN + 0] + s_part[r * WNN + 1] +
                       s_part[r * WNN + 2] + s_part[r * WNN + 3];
            v[i] = (r < len) ? sv : -3.0e38f;
        }
        float mx = fmaxf(v[0], fmaxf(v[1], v[2]));
        #pragma unroll
        for (int o = 16; o > 0; o >>= 1)
            mx = fmaxf(mx, __shfl_xor_sync(0xffffffffu, mx, o));
        float e[3];
        float ssum = 0.0f;
        #pragma unroll
        for (int i = 0; i < 3; i++) {
            int r = lane + 32 * i;
            e[i] = (r < len) ? __expf(v[i] - mx) : 0.0f;
            ssum += e[i];
        }
        #pragma unroll
        for (int o = 16; o > 0; o >>= 1)
            ssum += __shfl_xor_sync(0xffffffffu, ssum, o);
        float inv = 1.0f / ssum;
        #pragma unroll
        for (int i = 0; i < 3; i++) {
            int r = lane + 32 * i;
            attn_s[r] = (r < len) ? e[i] * inv : 0.0f;
        }
    }
    __syncthreads();

    // fused out GEMV: out[b,:] = sum_s attn_s[s] * x[b,start+s,:]
    {
        const float4* xb = x4 + (size_t)(b * Sn + start) * (En / 4);
        float4 a0 = make_float4(0.f, 0.f, 0.f, 0.f);
        float4 a1 = make_float4(0.f, 0.f, 0.f, 0.f);
        int s = 0;
        for (; s + 2 <= len; s += 2) {
            float w0 = attn_s[s], w1 = attn_s[s + 1];
            float4 v0 = xb[(size_t)s * (En / 4) + tid];
            float4 v1 = xb[(size_t)(s + 1) * (En / 4) + tid];
            a0.x += w0 * v0.x; a0.y += w0 * v0.y; a0.z += w0 * v0.z; a0.w += w0 * v0.w;
            a1.x += w1 * v1.x; a1.y += w1 * v1.y; a1.z += w1 * v1.z; a1.w += w1 * v1.w;
        }
        if (s < len) {
            float w0 = attn_s[s];
            float4 v0 = xb[(size_t)s * (En / 4) + tid];
            a0.x += w0 * v0.x; a0.y += w0 * v0.y; a0.z += w0 * v0.z; a0.w += w0 * v0.w;
        }
        a0.x += a1.x; a0.y += a1.y; a0.z += a1.z; a0.w += a1.w;
        reinterpret_cast<float4*>(out)[(size_t)b * (En / 4) + tid] = a0;
    }

    // fused keep_attention (last batch only): zeros outside the bag
    if (b == Bn - 1 && tid < Sn) {
        int r = tid - start;
        out[(size_t)Bn * En + tid] = (r >= 0 && r < len) ? attn_s[r] : 0.0f;
    }
}

// ---------------------------------------------------------------------------
extern "C" void kernel_launch(void* const* d_in, const int* in_sizes, int n_in,
                              void* d_out, int out_size) {
    const float* x   = (const float*)d_in[0];
    const float* W   = (const float*)d_in[1];
    const float* u   = (const float*)d_in[2];
    const int*   doc = (const int*)d_in[3];
    float* out = (float*)d_out;

    convW_kernel<<<1024, 256>>>((const float4*)W);
    convX_kernel<<<Bn, 256>>>((const float4*)x, doc);

    cudaFuncSetAttribute(scores_kernel,
                         cudaFuncAttributeMaxDynamicSharedMemorySize, SMEM_TOTAL);
    scores_kernel<<<Bn, NTHR, SMEM_TOTAL>>>((const float4*)x, u, doc, out);
}

// round 6
// speedup vs baseline: 3.1519x; 1.0655x over previous
#include <cuda_runtime.h>
#include <cuda_fp16.h>
#include <cstdint>
#include <cstddef>

#define Bn 256
#define Sn 128
#define En 1024

constexpr int MT   = 96;
constexpr int NT   = 128;           // f-columns per chunk
constexpr int KT   = 64;            // K halfs per tile (128B rows)
constexpr int NFC  = En / NT;       // 8
constexpr int NKT  = En / KT;       // 16
constexpr int TILES = NFC * NKT;    // 128
constexpr int NTHR = 256;           // 8 warps: 2 (M, interleaved subtiles) x 4 (N, 32 cols)
constexpr int WMN  = 2;
constexpr int WNN  = 4;
constexpr int STAGES = 3;

constexpr int A_TILE_B = MT * KT * 2;   // 12288
constexpr int B_TILE_B = NT * KT * 2;   // 16384
constexpr int STG_B    = A_TILE_B + B_TILE_B;          // 28672
constexpr int OFF_U    = STAGES * STG_B;               // 86016
constexpr int OFF_SP   = OFF_U + En * 4;               // 90112
constexpr int OFF_AT   = OFF_SP + MT * WNN * 4;        // 91648
constexpr int SMEM_TOTAL = OFF_AT + MT * 4;            // 92032

// device-global scratch (allocations are forbidden)
__device__ __half g_Wh[En * En];
__device__ __half g_xh[Bn * Sn * En];

// ---------------------------------------------------------------------------
__device__ __forceinline__ void cp16(uint32_t dst, const void* src, bool pred) {
    int sz = pred ? 16 : 0;
    asm volatile("cp.async.cg.shared.global [%0], [%1], 16, %2;\n"
                 :: "r"(dst), "l"(src), "r"(sz));
}
__device__ __forceinline__ void cp_commit() {
    asm volatile("cp.async.commit_group;\n");
}
__device__ __forceinline__ void cp_wait1() {
    asm volatile("cp.async.wait_group 1;\n");
}

__device__ __forceinline__ float tanha(float x) {
    float y;
    asm("tanh.approx.f32 %0, %1;" : "=f"(y) : "f"(x));
    return y;
}

__device__ __forceinline__ void ldsm4(uint32_t& r0, uint32_t& r1,
                                      uint32_t& r2, uint32_t& r3, uint32_t addr) {
    asm volatile("ldmatrix.sync.aligned.m8n8.x4.shared.b16 {%0,%1,%2,%3}, [%4];"
                 : "=r"(r0), "=r"(r1), "=r"(r2), "=r"(r3) : "r"(addr));
}

__device__ __forceinline__ void mma16816(float* c,
                                         uint32_t a0, uint32_t a1, uint32_t a2, uint32_t a3,
                                         uint32_t b0, uint32_t b1) {
    asm volatile(
        "mma.sync.aligned.m16n8k16.row.col.f32.f16.f16.f32 "
        "{%0,%1,%2,%3},{%4,%5,%6,%7},{%8,%9},{%0,%1,%2,%3};"
        : "+f"(c[0]), "+f"(c[1]), "+f"(c[2]), "+f"(c[3])
        : "r"(a0), "r"(a1), "r"(a2), "r"(a3), "r"(b0), "r"(b1));
}

// ---------------------------------------------------------------------------
// Pre-convert kernels (fp32 -> fp16)
// ---------------------------------------------------------------------------
__global__ __launch_bounds__(256)
void convW_kernel(const float4* __restrict__ W4) {
    int idx = blockIdx.x * 256 + threadIdx.x;       // 262144 float4s
    float4 v = W4[idx];
    __half2* o = reinterpret_cast<__half2*>(g_Wh);
    o[idx * 2]     = __floats2half2_rn(v.x, v.y);
    o[idx * 2 + 1] = __floats2half2_rn(v.z, v.w);
}

__global__ __launch_bounds__(256)
void convX_kernel(const float4* __restrict__ x4, const int* __restrict__ doc) {
    const int b = blockIdx.x;
    const int start = doc[2 * b];
    const int end   = doc[2 * b + 1];
    const int t = threadIdx.x;
    __half2* o = reinterpret_cast<__half2*>(g_xh);
    for (int s = start; s < end; s++) {
        size_t base = (size_t)(b * Sn + s) * (En / 4) + t;
        float4 v = x4[base];
        o[base * 2]     = __floats2half2_rn(v.x, v.y);
        o[base * 2 + 1] = __floats2half2_rn(v.z, v.w);
    }
}

// ---------------------------------------------------------------------------
// Kernel A: fused scores + softmax + out GEMV + keep_attention.
// ---------------------------------------------------------------------------
extern __shared__ char smem[];

__global__ __launch_bounds__(NTHR, 2)
void scores_kernel(const float4* __restrict__ x4,
                   const float* __restrict__ u,
                   const int* __restrict__ doc,
                   float* __restrict__ out) {
    const int b    = blockIdx.x;
    const int tid  = threadIdx.x;
    const int lane = tid & 31;
    const int wid  = tid >> 5;
    const int wm   = wid % WMN;       // subtiles st with st%2==wm (interleaved)
    const int wn   = wid / WMN;       // cols [wn*32, wn*32+32)
    const int g    = lane >> 2;
    const int tg   = lane & 3;

    const int start = doc[2 * b];
    const int len   = doc[2 * b + 1] - start;    // 1..96
    const int nmt   = (len + 15) >> 4;           // active 16-row subtiles (1..6)
    const int plen  = nmt << 4;                  // padded bag length (rows ever read)
    const int nms   = (nmt + 1 - wm) >> 1;       // this warp's active subtiles (0..3)

    const uint32_t smem_u32 = (uint32_t)__cvta_generic_to_shared(smem);
    float* u_s    = reinterpret_cast<float*>(smem + OFF_U);
    float* s_part = reinterpret_cast<float*>(smem + OFF_SP);
    float* attn_s = reinterpret_cast<float*>(smem + OFF_AT);

    for (int i = tid; i < En; i += NTHR) u_s[i] = u[i];
    for (int i = tid; i < MT * WNN; i += NTHR) s_part[i] = 0.0f;

    // fill-lane constants
    const int fa_m = tid >> 3;
    const int fa_c = tid & 7;

    auto fill = [&](int t, int buf) {
        const int fc = t >> 4;
        const int k0 = (t & 15) * KT;
        const uint32_t aBase = smem_u32 + buf * STG_B;
        const uint32_t bBase = aBase + A_TILE_B;
        #pragma unroll
        for (int i = 0; i < 3; i++) {           // 768 A chunks / 256 thr
            int m = fa_m + i * 32;
            if (m < plen) {                     // rows >= plen are never read: skip STS
                uint32_t dst = aBase + m * 128 + ((fa_c ^ (m & 7)) << 4);
                const __half* src = g_xh + (size_t)(b * Sn + start + m) * En + k0 + fa_c * 8;
                cp16(dst, src, m < len);        // zfill pads [len, plen)
            }
        }
        #pragma unroll
        for (int i = 0; i < 4; i++) {           // 1024 B chunks / 256 thr
            int n = fa_m + i * 32;
            uint32_t dst = bBase + n * 128 + ((fa_c ^ (n & 7)) << 4);
            const __half* src = g_Wh + (size_t)(fc * NT + n) * En + k0 + fa_c * 8;
            cp16(dst, src, true);
        }
        cp_commit();
    };

    float acc[3][4][4];
    #pragma unroll
    for (int ms = 0; ms < 3; ms++)
        #pragma unroll
        for (int j = 0; j < 4; j++)
            #pragma unroll
            for (int i = 0; i < 4; i++) acc[ms][j][i] = 0.0f;
    float sacc[3][2] = {{0.f,0.f},{0.f,0.f},{0.f,0.f}};

    // ldmatrix lane-address components
    const int a_row   = (lane & 15);
    const int a_choff = (lane >> 4);
    const int b_rowin = (lane & 7) + ((lane >> 4) << 3);
    const int b_choff = ((lane >> 3) & 1);

    // prologue: stage tiles 0 and 1
    fill(0, 0);
    fill(1, 1);

    for (int t = 0; t < TILES; t++) {
        cp_wait1();
        __syncthreads();
        if (t + 2 < TILES) fill(t + 2, (t + 2) % STAGES);
        else cp_commit();    // keep group count uniform

        const uint32_t aBase = smem_u32 + (t % STAGES) * STG_B;
        const uint32_t bBase = aBase + A_TILE_B;

        if (nms > 0) {
            #pragma unroll
            for (int ks = 0; ks < 4; ks++) {
                uint32_t af[3][4];
                #pragma unroll
                for (int ms = 0; ms < 3; ms++) {
                    if (ms < nms) {
                        int row = (2 * ms + wm) * 16 + a_row;   // interleaved subtile
                        int chv = 2 * ks + a_choff;
                        uint32_t addr = aBase + row * 128 + ((chv ^ (row & 7)) << 4);
                        ldsm4(af[ms][0], af[ms][1], af[ms][2], af[ms][3], addr);
                    }
                }
                uint32_t bf[2][4];
                #pragma unroll
                for (int jp = 0; jp < 2; jp++) {
                    int nrow = wn * 32 + jp * 16 + b_rowin;
                    int chv = 2 * ks + b_choff;
                    uint32_t addr = bBase + nrow * 128 + ((chv ^ (nrow & 7)) << 4);
                    ldsm4(bf[jp][0], bf[jp][1], bf[jp][2], bf[jp][3], addr);
                }
                #pragma unroll
                for (int ms = 0; ms < 3; ms++) {
                    if (ms < nms) {
                        #pragma unroll
                        for (int j = 0; j < 4; j++) {
                            mma16816(acc[ms][j],
                                     af[ms][0], af[ms][1], af[ms][2], af[ms][3],
                                     bf[j >> 1][(j & 1) * 2], bf[j >> 1][(j & 1) * 2 + 1]);
                        }
                    }
                }
            }
        }

        if ((t & 15) == 15) {
            const int fc = t >> 4;
            #pragma unroll
            for (int ms = 0; ms < 3; ms++) {
                if (ms < nms) {
                    #pragma unroll
                    for (int j = 0; j < 4; j++) {
                        int f = fc * NT + wn * 32 + j * 8 + 2 * tg;
                        float u0 = u_s[f], u1 = u_s[f + 1];
                        sacc[ms][0] += tanha(acc[ms][j][0]) * u0 + tanha(acc[ms][j][1]) * u1;
                        sacc[ms][1] += tanha(acc[ms][j][2]) * u0 + tanha(acc[ms][j][3]) * u1;
                        acc[ms][j][0] = 0.f; acc[ms][j][1] = 0.f;
                        acc[ms][j][2] = 0.f; acc[ms][j][3] = 0.f;
                    }
                }
            }
        }
    }

    // deterministic tg-reduction, write partials
    #pragma unroll
    for (int ms = 0; ms < 3; ms++) {
        #pragma unroll
        for (int rg = 0; rg < 2; rg++) {
            float v = sacc[ms][rg];
            v += __shfl_xor_sync(0xffffffffu, v, 1);
            v += __shfl_xor_sync(0xffffffffu, v, 2);
            if (ms < nms && tg == 0) {
                int row = (2 * ms + wm) * 16 + rg * 8 + g;
                s_part[row * WNN + wn] = v;
            }
        }
    }
    __syncthreads();

    // softmax over the bag — warp 0 (deterministic); result -> attn_s[0..95]
    if (wid == 0) {
        float v[3];
        #pragma unroll
        for (int i = 0; i < 3; i++) {
            int r = lane + 32 * i;
            float sv = s_part[r * WNN + 0] + s_part[r * WNN + 1] +
                       s_part[r * WNN + 2] + s_part[r * WNN + 3];
            v[i] = (r < len) ? sv : -3.0e38f;
        }
        float mx = fmaxf(v[0], fmaxf(v[1], v[2]));
        #pragma unroll
        for (int o = 16; o > 0; o >>= 1)
            mx = fmaxf(mx, __shfl_xor_sync(0xffffffffu, mx, o));
        float e[3];
        float ssum = 0.0f;
        #pragma unroll
        for (int i = 0; i < 3; i++) {
            int r = lane + 32 * i;
            e[i] = (r < len) ? __expf(v[i] - mx) : 0.0f;
            ssum += e[i];
        }
        #pragma unroll
        for (int o = 16; o > 0; o >>= 1)
            ssum += __shfl_xor_sync(0xffffffffu, ssum, o);
        float inv = 1.0f / ssum;
        #pragma unroll
        for (int i = 0; i < 3; i++) {
            int r = lane + 32 * i;
            attn_s[r] = (r < len) ? e[i] * inv : 0.0f;
        }
    }
    __syncthreads();

    // fused out GEMV: out[b,:] = sum_s attn_s[s] * x[b,start+s,:]
    {
        const float4* xb = x4 + (size_t)(b * Sn + start) * (En / 4);
        float4 a0 = make_float4(0.f, 0.f, 0.f, 0.f);
        float4 a1 = make_float4(0.f, 0.f, 0.f, 0.f);
        int s = 0;
        for (; s + 2 <= len; s += 2) {
            float w0 = attn_s[s], w1 = attn_s[s + 1];
            float4 v0 = xb[(size_t)s * (En / 4) + tid];
            float4 v1 = xb[(size_t)(s + 1) * (En / 4) + tid];
            a0.x += w0 * v0.x; a0.y += w0 * v0.y; a0.z += w0 * v0.z; a0.w += w0 * v0.w;
            a1.x += w1 * v1.x; a1.y += w1 * v1.y; a1.z += w1 * v1.z; a1.w += w1 * v1.w;
        }
        if (s < len) {
            float w0 = attn_s[s];
            float4 v0 = xb[(size_t)s * (En / 4) + tid];
            a0.x += w0 * v0.x; a0.y += w0 * v0.y; a0.z += w0 * v0.z; a0.w += w0 * v0.w;
        }
        a0.x += a1.x; a0.y += a1.y; a0.z += a1.z; a0.w += a1.w;
        reinterpret_cast<float4*>(out)[(size_t)b * (En / 4) + tid] = a0;
    }

    // fused keep_attention (last batch only): zeros outside the bag
    if (b == Bn - 1 && tid < Sn) {
        int r = tid - start;
        out[(size_t)Bn * En + tid] = (r >= 0 && r < len) ? attn_s[r] : 0.0f;
    }
}

// ---------------------------------------------------------------------------
extern "C" void kernel_launch(void* const* d_in, const int* in_sizes, int n_in,
                              void* d_out, int out_size) {
    const float* x   = (const float*)d_in[0];
    const float* W   = (const float*)d_in[1];
    const float* u   = (const float*)d_in[2];
    const int*   doc = (const int*)d_in[3];
    float* out = (float*)d_out;

    convW_kernel<<<1024, 256>>>((const float4*)W);
    convX_kernel<<<Bn, 256>>>((const float4*)x, doc);

    cudaFuncSetAttribute(scores_kernel,
                         cudaFuncAttributeMaxDynamicSharedMemorySize, SMEM_TOTAL);
    scores_kernel<<<Bn, NTHR, SMEM_TOTAL>>>((const float4*)x, u, doc, out);
}